// round 5
// baseline (speedup 1.0000x reference)
#include <cuda_runtime.h>
#include <cuda_fp16.h>
#include <math.h>
#include <stdint.h>

// Problem constants
#define BB    16
#define CC    64
#define HWSZ  4096
#define NPIX  65536
#define KK    1024
#define DD    64
#define NEL   4194304
#define GATHER_BLOCKS 4096     // NEL / 4 / 256
#define MARGIN 1.5e-3f         // coarse-key units (= half of score units)

// Device scratch
__device__ __align__(16) int    g_idx[NPIX];
__device__ float  g_counts[KK];
__device__ float  g_cnorm[KK];
__device__ float  g_part[GATHER_BLOCKS];
__device__ __align__(16) __half g_cbh[KK * 72];     // [-c] fp16, rows padded to 72 (144B)
__device__ __align__(4)  __half g_cnb[KK];          // fl16(0.375 + cn/2)

// ---------------------------------------------------------------------------
// warp-MMA helpers (standard PTX, no sm_103a-only features)
// ---------------------------------------------------------------------------
__device__ __forceinline__ void ldm_x4(uint32_t& r0, uint32_t& r1,
                                       uint32_t& r2, uint32_t& r3, uint32_t a) {
    asm volatile("ldmatrix.sync.aligned.m8n8.x4.shared.b16 {%0,%1,%2,%3}, [%4];"
                 : "=r"(r0), "=r"(r1), "=r"(r2), "=r"(r3) : "r"(a));
}
__device__ __forceinline__ void mma16816(uint32_t& d0, uint32_t& d1,
                                         uint32_t a0, uint32_t a1, uint32_t a2, uint32_t a3,
                                         uint32_t b0, uint32_t b1) {
    asm volatile("mma.sync.aligned.m16n8k16.row.col.f16.f16.f16.f16 "
                 "{%0,%1}, {%2,%3,%4,%5}, {%6,%7}, {%0,%1};"
                 : "+r"(d0), "+r"(d1)
                 : "r"(a0), "r"(a1), "r"(a2), "r"(a3), "r"(b0), "r"(b1));
}
__device__ __forceinline__ uint32_t hmin2u(uint32_t a, uint32_t b) {
    uint32_t d;
    asm volatile("min.f16x2 %0, %1, %2;" : "=r"(d) : "r"(a), "r"(b));
    return d;
}
__device__ __forceinline__ uint32_t hadd2u(uint32_t a, uint32_t b) {
    uint32_t d;
    asm volatile("add.f16x2 %0, %1, %2;" : "=r"(d) : "r"(a), "r"(b));
    return d;
}

// SMEM layout (bytes)
#define SM_AS    0                       // 128 rows x 144B  = 18432
#define SM_BS    18432                   // 128 rows x 144B  = 18432
#define SM_SBUF  36864                   // 128 rows x 272B  = 34816
#define SM_CNB   71680                   // 512 x u32        = 2048
#define SM_NS    73728                   // 128 x f32        = 512
#define SM_TOTAL 74240

// ---------------------------------------------------------------------------
// Kernel 1: prep — exact cnorm, negated fp16 codebook image, bias halves
// ---------------------------------------------------------------------------
__global__ void prep_kernel(const float* __restrict__ cb) {
    int k = blockIdx.x * 256 + threadIdx.x;
    if (k >= KK) return;
    float s = 0.f;
    #pragma unroll
    for (int d = 0; d < DD; d++) {
        float v = cb[k * DD + d];
        s = __fadd_rn(s, __fmul_rn(v, v));
        g_cbh[k * 72 + d] = __float2half(-v);
    }
    #pragma unroll
    for (int d = DD; d < 72; d++) g_cbh[k * 72 + d] = __float2half(0.f);
    g_cnorm[k]  = s;
    g_cnb[k]    = __float2half(0.375f + 0.5f * s);
    g_counts[k] = 0.f;
}

// ---------------------------------------------------------------------------
// Kernel 2: coarse tensor-core scores + candidate filter + exact argmin
// 256 threads (8 warps), 128 pixels/block; warp w owns pixels w*16..w*16+15
// ---------------------------------------------------------------------------
__global__ void __launch_bounds__(256, 2)
coarse_kernel(const float* __restrict__ in, const float* __restrict__ cb) {
    extern __shared__ char sm[];
    __half* As   = (__half*)(sm + SM_AS);      // [p][72] fp16 x
    __half* Bs   = (__half*)(sm + SM_BS);      // [n][72] fp16 -c (chunk)
    __half* sbuf = (__half*)(sm + SM_SBUF);    // [p][136] fp16 scores (chunk)
    uint32_t* cnbs = (uint32_t*)(sm + SM_CNB); // 512 f16x2 bias pairs
    float* nss   = (float*)(sm + SM_NS);       // [128] exact ||x||^2

    const int tid  = threadIdx.x;
    const int wid  = tid >> 5;
    const int lane = tid & 31;
    const int n0px = blockIdx.x * 128;          // never crosses batch boundary
    const int bb   = n0px >> 12;
    const int hw0  = n0px & 4095;
    const float* xin = in + (size_t)bb * CC * HWSZ + hw0;

    // ---- init: As (fp16 x), cnb pairs, ns (exact sequential chain) ----
    for (int i = tid; i < 8192; i += 256) {
        int d = i >> 7, p = i & 127;
        As[p * 72 + d] = __float2half(xin[(size_t)d * HWSZ + p]);
    }
    for (int i = tid; i < 512; i += 256) cnbs[i] = ((const uint32_t*)g_cnb)[i];
    if (tid < 128) {
        float s = 0.f;
        #pragma unroll
        for (int d = 0; d < DD; d++) {
            float v = xin[(size_t)d * HWSZ + tid];
            s = __fadd_rn(s, __fmul_rn(v, v));
        }
        nss[tid] = s;
    }
    __syncthreads();

    // ---- A fragments (constant across chunks): 4 ksteps x 4 regs ----
    const uint32_t As_b = (uint32_t)__cvta_generic_to_shared(As);
    uint32_t A[4][4];
    {
        int p0  = wid * 16;
        int row = p0 + (lane & 7) + 8 * ((lane >> 3) & 1);
        int colq = 8 * (lane >> 4);
        #pragma unroll
        for (int ks = 0; ks < 4; ks++) {
            uint32_t a = As_b + (uint32_t)(row * 144 + (ks * 16 + colq) * 2);
            ldm_x4(A[ks][0], A[ks][1], A[ks][2], A[ks][3], a);
        }
    }

    const uint32_t Bs_b = (uint32_t)__cvta_generic_to_shared(Bs);
    const uint32_t sb_b = (uint32_t)__cvta_generic_to_shared(sbuf);

    const int qr    = lane >> 2;            // 0..7
    const int qc    = lane & 3;             // 0..3
    const int r0    = wid * 16 + qr;        // block-local pixel rows
    const int r1    = r0 + 8;
    const int xg0   = hw0 + r0;             // global x addr parts for refine
    const int xg1   = hw0 + r1;
    const float* xbase = in + (size_t)bb * CC * HWSZ;

    uint32_t m0 = 0x7C007C00u, m1 = 0x7C007C00u;      // +inf f16x2
    unsigned long long best0 = ~0ull, best1 = ~0ull;  // (bits(exact)<<32)|n

    const uint32_t bfrag0 = Bs_b + (uint32_t)((lane & 7) * 144 + (lane >> 3) * 16);
    const uint32_t st0 = sb_b + (uint32_t)(r0 * 272 + 2 * qc * 2);
    const uint32_t st1 = sb_b + (uint32_t)(r1 * 272 + 2 * qc * 2);

    for (int ch = 0; ch < 8; ch++) {
        __syncthreads();   // prior chunk pass2 done everywhere
        // copy Bs chunk: 128 rows x 144B = 1152 float4
        {
            const float4* src = (const float4*)((const char*)g_cbh + ch * 18432);
            float4* dst = (float4*)Bs;
            #pragma unroll
            for (int i = 0; i < 5; i++) {
                int j = tid + i * 256;
                if (j < 1152) dst[j] = src[j];
            }
        }
        __syncthreads();

        // ---- pass 1: 16 n-tiles of 8 codes ----
        uint32_t bb_addr = bfrag0;
        #pragma unroll 4
        for (int nt = 0; nt < 16; nt++) {
            uint32_t b0, b1, b2, b3, b4, b5, b6, b7;
            ldm_x4(b0, b1, b2, b3, bb_addr);        // ksteps 0,1
            ldm_x4(b4, b5, b6, b7, bb_addr + 64);   // ksteps 2,3
            uint32_t d0 = 0u, d1 = 0u;
            mma16816(d0, d1, A[0][0], A[0][1], A[0][2], A[0][3], b0, b1);
            mma16816(d0, d1, A[1][0], A[1][1], A[1][2], A[1][3], b2, b3);
            mma16816(d0, d1, A[2][0], A[2][1], A[2][2], A[2][3], b4, b5);
            mma16816(d0, d1, A[3][0], A[3][1], A[3][2], A[3][3], b6, b7);
            uint32_t cnb = cnbs[ch * 64 + nt * 4 + qc];
            d0 = hadd2u(d0, cnb);
            d1 = hadd2u(d1, cnb);
            m0 = hmin2u(m0, d0);
            m1 = hmin2u(m1, d1);
            *(uint32_t*)((char*)sbuf + (st0 - sb_b) + nt * 16) = d0;
            *(uint32_t*)((char*)sbuf + (st1 - sb_b) + nt * 16) = d1;
            bb_addr += 8 * 144;
        }

        // ---- per-row threshold (quad + halves reduce of running min) ----
        uint32_t q0 = hmin2u(m0, __shfl_xor_sync(0xffffffffu, m0, 1));
        q0 = hmin2u(q0, __shfl_xor_sync(0xffffffffu, q0, 2));
        uint32_t q1 = hmin2u(m1, __shfl_xor_sync(0xffffffffu, m1, 1));
        q1 = hmin2u(q1, __shfl_xor_sync(0xffffffffu, q1, 2));
        __half2 h0 = *(__half2*)&q0, h1 = *(__half2*)&q1;
        float rm0 = fminf(__low2float(h0), __high2float(h0));
        float rm1 = fminf(__low2float(h1), __high2float(h1));
        __half  t0h = __float2half_ru(rm0 + MARGIN);
        __half  t1h = __float2half_ru(rm1 + MARGIN);
        uint32_t thr0, thr1;
        { __half2 t2 = __half2half2(t0h); thr0 = *(uint32_t*)&t2; }
        { __half2 t2 = __half2half2(t1h); thr1 = *(uint32_t*)&t2; }

        __syncwarp();

        // ---- pass 2: scan 32 codes per row slice, refine hits exactly ----
        #pragma unroll
        for (int rr = 0; rr < 2; rr++) {
            const uint32_t thr = rr ? thr1 : thr0;
            const __half  thh = rr ? t1h : t0h;
            const char* rowp = (const char*)sbuf + (rr ? r1 : r0) * 272 + qc * 64;
            const float ns   = nss[rr ? r1 : r0];
            const float* xg  = xbase + (rr ? xg1 : xg0);
            unsigned long long bst = rr ? best1 : best0;
            #pragma unroll
            for (int j = 0; j < 8; j++) {
                uint2 v = *(const uint2*)(rowp + j * 8);
                uint32_t u = hmin2u(hmin2u(v.x, v.y), thr);
                if (u != thr) {
                    // rare: decode which of the 4 halves are candidates
                    __half hv[4];
                    *(uint32_t*)&hv[0] = v.x;
                    *(uint32_t*)&hv[2] = v.y;
                    #pragma unroll
                    for (int e = 0; e < 4; e++) {
                        if (__hlt(hv[e], thh)) {
                            int n = ch * 128 + qc * 32 + j * 4 + e;
                            const float* crow = cb + n * DD;
                            float acc = 0.f;
                            #pragma unroll
                            for (int d = 0; d < DD; d++)
                                acc = __fmaf_rn(__ldg(&xg[(size_t)d * HWSZ]),
                                                __ldg(&crow[d]), acc);
                            float s = __fsub_rn(__fadd_rn(ns, __ldg(&g_cnorm[n])),
                                                __fmul_rn(2.0f, acc));
                            unsigned long long key =
                                ((unsigned long long)__float_as_uint(s) << 32) |
                                (unsigned long long)n;
                            if (key < bst) bst = key;
                        }
                    }
                }
            }
            if (rr) best1 = bst; else best0 = bst;
        }
    }

    // ---- final quad reduce + write index / histogram ----
    {
        unsigned long long b0k = best0, b1k = best1, o;
        o = __shfl_xor_sync(0xffffffffu, b0k, 1); if (o < b0k) b0k = o;
        o = __shfl_xor_sync(0xffffffffu, b0k, 2); if (o < b0k) b0k = o;
        o = __shfl_xor_sync(0xffffffffu, b1k, 1); if (o < b1k) b1k = o;
        o = __shfl_xor_sync(0xffffffffu, b1k, 2); if (o < b1k) b1k = o;
        if (qc == 0) {
            int i0 = (int)(b0k & 0xffffffffull);
            int i1 = (int)(b1k & 0xffffffffull);
            g_idx[n0px + r0] = i0;
            g_idx[n0px + r1] = i1;
            atomicAdd(&g_counts[i0], 1.0f);
            atomicAdd(&g_counts[i1], 1.0f);
        }
    }
}

// ---------------------------------------------------------------------------
// Kernel 3: gather quantized output + per-block loss partial.
// Loads are vectorized (in and g_idx are 16B-aligned); the OUTPUT pointer is
// out+1 (4 mod 16), so stores MUST be scalar — float4 store here crashes.
// ---------------------------------------------------------------------------
__global__ void gather_loss_kernel(const float* __restrict__ in,
                                   const float* __restrict__ cb,
                                   float* __restrict__ outq) {
    const int tid = threadIdx.x;
    const int e   = (blockIdx.x * 256 + tid) * 4;

    int b  = e >> 18;
    int r  = e & 262143;
    int c  = r >> 12;
    int hw = r & 4095;           // multiple of 4
    const int4 gi = *(const int4*)&g_idx[(b << 12) | hw];

    float4 x = *(const float4*)(in + e);
    float q0 = __ldg(&cb[gi.x * DD + c]);
    float q1 = __ldg(&cb[gi.y * DD + c]);
    float q2 = __ldg(&cb[gi.z * DD + c]);
    float q3 = __ldg(&cb[gi.w * DD + c]);

    float d0 = q0 - x.x, d1 = q1 - x.y, d2 = q2 - x.z, d3 = q3 - x.w;
    outq[e + 0] = x.x + d0;      // scalar stores: outq is 4-mod-16 aligned
    outq[e + 1] = x.y + d1;
    outq[e + 2] = x.z + d2;
    outq[e + 3] = x.w + d3;
    float part = d0 * d0 + d1 * d1 + d2 * d2 + d3 * d3;

    #pragma unroll
    for (int o2 = 16; o2; o2 >>= 1)
        part += __shfl_xor_sync(0xffffffffu, part, o2);
    __shared__ float ws[8];
    if ((tid & 31) == 0) ws[tid >> 5] = part;
    __syncthreads();
    if (tid == 0) {
        float s = 0.f;
        #pragma unroll
        for (int w = 0; w < 8; w++) s += ws[w];
        g_part[blockIdx.x] = s;
    }
}

// ---------------------------------------------------------------------------
// Kernel 4: finalize loss + perplexity
// ---------------------------------------------------------------------------
__global__ void finalize_kernel(const float* __restrict__ beta,
                                float* __restrict__ loss_out,
                                float* __restrict__ pp_out) {
    const int t = threadIdx.x;   // 1024

    float ls = 0.f;
    #pragma unroll
    for (int i = 0; i < GATHER_BLOCKS / 1024; i++)
        ls += g_part[t * (GATHER_BLOCKS / 1024) + i];

    float em  = g_counts[t] * (1.0f / (float)NPIX);
    float ent = em * logf(em + 1e-10f);

    #pragma unroll
    for (int o = 16; o; o >>= 1) {
        ls  += __shfl_xor_sync(0xffffffffu, ls, o);
        ent += __shfl_xor_sync(0xffffffffu, ent, o);
    }
    __shared__ float wl[32], we[32];
    if ((t & 31) == 0) { wl[t >> 5] = ls; we[t >> 5] = ent; }
    __syncthreads();
    if (t == 0) {
        float tl = 0.f, te = 0.f;
        #pragma unroll
        for (int w = 0; w < 32; w++) { tl += wl[w]; te += we[w]; }
        float mean = tl / (float)NEL;
        *loss_out = (1.0f + *beta) * 10.0f * mean;   // KLD_SCALE = 10
        *pp_out   = expf(-te);
    }
}

// ---------------------------------------------------------------------------
// Launch
// ---------------------------------------------------------------------------
extern "C" void kernel_launch(void* const* d_in, const int* in_sizes, int n_in,
                              void* d_out, int out_size) {
    const float* in   = nullptr;
    const float* cb   = nullptr;
    const float* beta = nullptr;
    for (int i = 0; i < n_in; i++) {
        if      (in_sizes[i] == NEL)     in   = (const float*)d_in[i];
        else if (in_sizes[i] == KK * DD) cb   = (const float*)d_in[i];
        else if (in_sizes[i] == 1)       beta = (const float*)d_in[i];
    }

    float* out      = (float*)d_out;
    float* loss_out = out;
    float* q_out    = out + 1;
    float* pp_out   = out + (out_size - 1);

    cudaFuncSetAttribute(coarse_kernel,
                         cudaFuncAttributeMaxDynamicSharedMemorySize, SM_TOTAL);

    prep_kernel<<<(KK + 255) / 256, 256>>>(cb);
    coarse_kernel<<<NPIX / 128, 256, SM_TOTAL>>>(in, cb);
    gather_loss_kernel<<<GATHER_BLOCKS, 256>>>(in, cb, q_out);
    finalize_kernel<<<1, 1024>>>(beta, loss_out, pp_out);
}

// round 6
// speedup vs baseline: 5.2142x; 5.2142x over previous
#include <cuda_runtime.h>
#include <math.h>
#include <stdint.h>

// Problem constants
#define BB    16
#define CC    64
#define HWSZ  4096
#define NPIX  65536
#define KK    1024
#define DD    64
#define NEL   4194304
#define TILE_P 128
#define CHUNK  128
#define GATHER_BLOCKS 4096     // NEL / 4 / 256

// Device scratch
__device__ __align__(16) int g_idx[NPIX];
__device__ float g_counts[KK];
__device__ float g_cnorm[KK];
__device__ float g_part[GATHER_BLOCKS];

// f32x2 packed helpers (Blackwell FFMA2 — ptxas never auto-generates these)
#define PACK2(dst, lo, hi) \
    asm("mov.b64 %0, {%1, %2};" : "=l"(dst) : "f"(lo), "f"(hi))
#define UNPACK2(lo, hi, src) \
    asm("mov.b64 {%0, %1}, %2;" : "=f"(lo), "=f"(hi) : "l"(src))
#define FMA2(acc, a, b) \
    asm("fma.rn.f32x2 %0, %1, %2, %0;" : "+l"(acc) : "l"(a), "l"(b))

// ---------------------------------------------------------------------------
// Kernel 1: codebook norms (XLA-style rounded mul+add, d ascending) + zeros
// ---------------------------------------------------------------------------
__global__ void prep_kernel(const float* __restrict__ cb) {
    int t = blockIdx.x * blockDim.x + threadIdx.x;
    if (t < KK) {
        float s = 0.f;
        #pragma unroll
        for (int d = 0; d < DD; d++) {
            float v = cb[t * DD + d];
            s = __fadd_rn(s, __fmul_rn(v, v));
        }
        g_cnorm[t]  = s;
        g_counts[t] = 0.f;
    }
}

// ---------------------------------------------------------------------------
// Kernel 2: exact argmin via packed-fp32 (FFMA2) GEMM + histogram
// smem: xs[64][128] f32 (32KB) | cs[64][132] f32 (33.8KB) | cns[128] | nss[128]
// ---------------------------------------------------------------------------
extern __shared__ float smem[];

__global__ void __launch_bounds__(256, 2)
argmin_kernel(const float* __restrict__ in, const float* __restrict__ cb) {
    float* xs  = smem;                       // 8192 floats
    float* cs  = smem + 8192;                // 8448 floats
    float* cns = smem + 8192 + 8448;         // 128
    float* nss = cns + 128;                  // 128

    const int tid = threadIdx.x;
    const int tx  = tid & 15;   // pixel group: pixels tx*8 .. tx*8+7
    const int ty  = tid >> 4;   // code group:  codes  ty*8 .. ty*8+7 (in chunk)

    const int n0  = blockIdx.x * TILE_P;     // tile never crosses batch boundary
    const int b   = n0 >> 12;
    const int hw0 = n0 & 4095;
    const float* xin = in + (size_t)b * CC * HWSZ + hw0;

    // load x tile: xs[d][p] = in[b, d, hw0+p]  (coalesced)
    for (int i = tid; i < 64 * 128; i += 256) {
        int d = i >> 7, p = i & 127;
        xs[d * 128 + p] = xin[(size_t)d * HWSZ + p];
    }
    __syncthreads();

    // per-pixel ||x||^2, exact sequential chain (reference rounding)
    if (tid < 128) {
        float s = 0.f;
        #pragma unroll
        for (int d = 0; d < DD; d++) {
            float v = xs[d * 128 + tid];
            s = __fadd_rn(s, __fmul_rn(v, v));
        }
        nss[tid] = s;
    }

    float bd[8];
    int   bi[8];
    #pragma unroll
    for (int i = 0; i < 8; i++) { bd[i] = 3.4e38f; bi[i] = 0; }

    unsigned long long acc2[4][8];

    for (int kc = 0; kc < KK; kc += CHUNK) {
        __syncthreads();
        // load codebook chunk transposed: cs[d][k] = cb[kc+k][d]
        for (int i = tid; i < CHUNK * 64; i += 256) {
            int k = i >> 6, d = i & 63;
            cs[d * 132 + k] = cb[(size_t)(kc + k) * DD + d];
        }
        if (tid < CHUNK) cns[tid] = g_cnorm[kc + tid];
        __syncthreads();

        #pragma unroll
        for (int i = 0; i < 4; i++)
            #pragma unroll
            for (int j = 0; j < 8; j++) acc2[i][j] = 0ull;

        // packed dot: each u64 lane is an independent, correctly-rounded
        // sequential-d fp32 FMA chain (bit-identical to the scalar version)
        #pragma unroll 2
        for (int d = 0; d < 64; d++) {
            const float4 xa = *reinterpret_cast<const float4*>(&xs[d * 128 + tx * 8]);
            const float4 xb = *reinterpret_cast<const float4*>(&xs[d * 128 + tx * 8 + 4]);
            const float4 ca = *reinterpret_cast<const float4*>(&cs[d * 132 + ty * 8]);
            const float4 cc = *reinterpret_cast<const float4*>(&cs[d * 132 + ty * 8 + 4]);
            unsigned long long xp[4], cd[8];
            PACK2(xp[0], xa.x, xa.y);  PACK2(xp[1], xa.z, xa.w);
            PACK2(xp[2], xb.x, xb.y);  PACK2(xp[3], xb.z, xb.w);
            PACK2(cd[0], ca.x, ca.x);  PACK2(cd[1], ca.y, ca.y);
            PACK2(cd[2], ca.z, ca.z);  PACK2(cd[3], ca.w, ca.w);
            PACK2(cd[4], cc.x, cc.x);  PACK2(cd[5], cc.y, cc.y);
            PACK2(cd[6], cc.z, cc.z);  PACK2(cd[7], cc.w, cc.w);
            #pragma unroll
            for (int i = 0; i < 4; i++)
                #pragma unroll
                for (int j = 0; j < 8; j++)
                    FMA2(acc2[i][j], xp[i], cd[j]);
        }

        // running min update. Reference score fl(fl(ns+cn) - fl(2*dot)):
        // 2*dot is exact in fp32, so fmaf(-2, dot, fl(ns+cn)) is bit-identical.
        // ascending k + strict '<' keeps first-index min within this thread.
        #pragma unroll
        for (int i2 = 0; i2 < 4; i2++) {
            float ns0 = nss[tx * 8 + i2 * 2];
            float ns1 = nss[tx * 8 + i2 * 2 + 1];
            #pragma unroll
            for (int j = 0; j < 8; j++) {
                float lo, hi;
                UNPACK2(lo, hi, acc2[i2][j]);
                float cn = cns[ty * 8 + j];
                float s0 = __fmaf_rn(-2.0f, lo, __fadd_rn(ns0, cn));
                float s1 = __fmaf_rn(-2.0f, hi, __fadd_rn(ns1, cn));
                int n = kc + ty * 8 + j;
                if (s0 < bd[i2 * 2])     { bd[i2 * 2]     = s0; bi[i2 * 2]     = n; }
                if (s1 < bd[i2 * 2 + 1]) { bd[i2 * 2 + 1] = s1; bi[i2 * 2 + 1] = n; }
            }
        }
    }

    // cross-thread (over ty) min reduction, reusing smem
    __syncthreads();
    float* rd = smem;                     // [16][128]
    int*   ri = (int*)(smem + 2048);      // [16][128]
    #pragma unroll
    for (int i = 0; i < 8; i++) {
        rd[ty * 128 + tx * 8 + i] = bd[i];
        ri[ty * 128 + tx * 8 + i] = bi[i];
    }
    __syncthreads();
    if (tid < 128) {
        float best = rd[tid];
        int   bidx = ri[tid];
        // explicit first-index tiebreak
        for (int t = 1; t < 16; t++) {
            float v  = rd[t * 128 + tid];
            int   vi = ri[t * 128 + tid];
            if (v < best || (v == best && vi < bidx)) { best = v; bidx = vi; }
        }
        g_idx[n0 + tid] = bidx;
        atomicAdd(&g_counts[bidx], 1.0f);   // integer-valued: deterministic
    }
}

// ---------------------------------------------------------------------------
// Kernel 3: gather quantized output + per-block loss partial.
// Loads vectorized (in / g_idx 16B-aligned); outq is out+1 (4 mod 16) so
// stores must stay scalar.
// ---------------------------------------------------------------------------
__global__ void gather_loss_kernel(const float* __restrict__ in,
                                   const float* __restrict__ cb,
                                   float* __restrict__ outq) {
    const int tid = threadIdx.x;
    const int e   = (blockIdx.x * 256 + tid) * 4;

    int b  = e >> 18;
    int r  = e & 262143;
    int c  = r >> 12;
    int hw = r & 4095;           // multiple of 4
    const int4 gi = *(const int4*)&g_idx[(b << 12) | hw];

    float4 x = *(const float4*)(in + e);
    float q0 = __ldg(&cb[gi.x * DD + c]);
    float q1 = __ldg(&cb[gi.y * DD + c]);
    float q2 = __ldg(&cb[gi.z * DD + c]);
    float q3 = __ldg(&cb[gi.w * DD + c]);

    float d0 = q0 - x.x, d1 = q1 - x.y, d2 = q2 - x.z, d3 = q3 - x.w;
    outq[e + 0] = x.x + d0;
    outq[e + 1] = x.y + d1;
    outq[e + 2] = x.z + d2;
    outq[e + 3] = x.w + d3;
    float part = d0 * d0 + d1 * d1 + d2 * d2 + d3 * d3;

    #pragma unroll
    for (int o2 = 16; o2; o2 >>= 1)
        part += __shfl_xor_sync(0xffffffffu, part, o2);
    __shared__ float ws[8];
    if ((tid & 31) == 0) ws[tid >> 5] = part;
    __syncthreads();
    if (tid == 0) {
        float s = 0.f;
        #pragma unroll
        for (int w = 0; w < 8; w++) s += ws[w];
        g_part[blockIdx.x] = s;
    }
}

// ---------------------------------------------------------------------------
// Kernel 4: finalize loss + perplexity
// ---------------------------------------------------------------------------
__global__ void finalize_kernel(const float* __restrict__ beta,
                                float* __restrict__ loss_out,
                                float* __restrict__ pp_out) {
    const int t = threadIdx.x;   // 1024

    float ls = 0.f;
    #pragma unroll
    for (int i = 0; i < GATHER_BLOCKS / 1024; i++)
        ls += g_part[t * (GATHER_BLOCKS / 1024) + i];

    float em  = g_counts[t] * (1.0f / (float)NPIX);
    float ent = em * logf(em + 1e-10f);

    #pragma unroll
    for (int o = 16; o; o >>= 1) {
        ls  += __shfl_xor_sync(0xffffffffu, ls, o);
        ent += __shfl_xor_sync(0xffffffffu, ent, o);
    }
    __shared__ float wl[32], we[32];
    if ((t & 31) == 0) { wl[t >> 5] = ls; we[t >> 5] = ent; }
    __syncthreads();
    if (t == 0) {
        float tl = 0.f, te = 0.f;
        #pragma unroll
        for (int w = 0; w < 32; w++) { tl += wl[w]; te += we[w]; }
        float mean = tl / (float)NEL;
        *loss_out = (1.0f + *beta) * 10.0f * mean;   // KLD_SCALE = 10
        *pp_out   = expf(-te);
    }
}

// ---------------------------------------------------------------------------
// Launch
// ---------------------------------------------------------------------------
extern "C" void kernel_launch(void* const* d_in, const int* in_sizes, int n_in,
                              void* d_out, int out_size) {
    const float* in   = nullptr;
    const float* cb   = nullptr;
    const float* beta = nullptr;
    for (int i = 0; i < n_in; i++) {
        if      (in_sizes[i] == NEL)     in   = (const float*)d_in[i];
        else if (in_sizes[i] == KK * DD) cb   = (const float*)d_in[i];
        else if (in_sizes[i] == 1)       beta = (const float*)d_in[i];
    }

    float* out      = (float*)d_out;
    float* loss_out = out;
    float* q_out    = out + 1;
    float* pp_out   = out + (out_size - 1);

    const int smem_bytes = (8192 + 8448 + 128 + 128) * 4;   // 67584
    cudaFuncSetAttribute(argmin_kernel,
                         cudaFuncAttributeMaxDynamicSharedMemorySize, smem_bytes);

    prep_kernel<<<(KK + 255) / 256, 256>>>(cb);
    argmin_kernel<<<NPIX / TILE_P, 256, smem_bytes>>>(in, cb);
    gather_loss_kernel<<<GATHER_BLOCKS, 256>>>(in, cb, q_out);
    finalize_kernel<<<1, 1024>>>(beta, loss_out, pp_out);
}